// round 1
// baseline (speedup 1.0000x reference)
#include <cuda_runtime.h>
#include <math.h>

#define N_NODES 40000
#define N_EDGES 640000
#define D 128
#define R 32
#define NB 8
#define XB_COLS 1152   // 9*128: 8 bases + loop

// ---- scratch (static device globals; no runtime allocation) ----
__device__ float g_xb[(size_t)N_NODES * XB_COLS];   // 184 MB
__device__ float g_s[(size_t)N_NODES * R];          // 5.1 MB
__device__ float g_ex[N_EDGES];
__device__ float g_denom[N_NODES];
__device__ float g_accum[(size_t)N_NODES * D];      // 20.5 MB
__device__ float g_ft[(size_t)N_NODES * D];         // 20.5 MB
__device__ float g_colsum[D];
__device__ float g_colsumsq[D];
__device__ float g_scale[D];
__device__ float g_shift[D];

// ---------------- zero init (graph-replay safe) ----------------
__global__ void k_zero() {
    int idx = blockIdx.x * blockDim.x + threadIdx.x;
    int stride = gridDim.x * blockDim.x;
    for (int j = idx; j < N_NODES * D; j += stride) g_accum[j] = 0.f;
    for (int j = idx; j < N_NODES; j += stride) g_denom[j] = 0.f;
    if (idx < D) { g_colsum[idx] = 0.f; g_colsumsq[idx] = 0.f; }
}

// ---------------- GEMM: xb = x @ [w_bases(b) | w_loop] ----------------
// M=40000, N=1152 (9 col-blocks of 128), K=128. fp32, 128x128x32 tiles, 8x8 micro.
#define BM 128
#define BN 128
#define BK 32
#define TM 8
#define TN 8

__global__ __launch_bounds__(256) void k_gemm(const float* __restrict__ x,
                                              const float* __restrict__ w_bases,
                                              const float* __restrict__ w_loop) {
    __shared__ __align__(16) float As[BK][BM];  // transposed: As[k][m]
    __shared__ __align__(16) float Bs[BK][BN];

    const int bc = blockIdx.x;                   // 0..8 (col block == basis)
    const int m0 = blockIdx.y * BM;
    const float* Bp = (bc < 8) ? (w_bases + (size_t)bc * D * D) : w_loop;
    const int tid = threadIdx.x;
    const int tx = tid & 15;
    const int ty = tid >> 4;

    float acc[TM][TN];
#pragma unroll
    for (int i = 0; i < TM; i++)
#pragma unroll
        for (int j = 0; j < TN; j++) acc[i][j] = 0.f;

    for (int k0 = 0; k0 < D; k0 += BK) {
        // load A tile (128x32) transposed into As
#pragma unroll
        for (int l = 0; l < 4; l++) {
            int lin = l * 256 + tid;           // 0..1023 float4 slots
            int m = lin >> 3;                  // 0..127
            int k4 = lin & 7;                  // 0..7
            int gm = m0 + m;
            float4 v = make_float4(0.f, 0.f, 0.f, 0.f);
            if (gm < N_NODES) v = *(const float4*)(x + (size_t)gm * D + k0 + k4 * 4);
            As[k4 * 4 + 0][m] = v.x;
            As[k4 * 4 + 1][m] = v.y;
            As[k4 * 4 + 2][m] = v.z;
            As[k4 * 4 + 3][m] = v.w;
        }
        // load B tile (32x128)
#pragma unroll
        for (int l = 0; l < 4; l++) {
            int lin = l * 256 + tid;
            int k = lin >> 5;                  // 0..31
            int n4 = lin & 31;                 // 0..31
            *(float4*)(&Bs[k][n4 * 4]) = *(const float4*)(Bp + (size_t)(k0 + k) * D + n4 * 4);
        }
        __syncthreads();

#pragma unroll
        for (int k = 0; k < BK; k++) {
            float ra[TM], rb[TN];
#pragma unroll
            for (int i = 0; i < TM; i += 4) *(float4*)(ra + i) = *(const float4*)(&As[k][ty * TM + i]);
#pragma unroll
            for (int j = 0; j < TN; j += 4) *(float4*)(rb + j) = *(const float4*)(&Bs[k][tx * TN + j]);
#pragma unroll
            for (int i = 0; i < TM; i++)
#pragma unroll
                for (int j = 0; j < TN; j++) acc[i][j] += ra[i] * rb[j];
        }
        __syncthreads();
    }

#pragma unroll
    for (int i = 0; i < TM; i++) {
        int gm = m0 + ty * TM + i;
        if (gm < N_NODES) {
            float* dst = g_xb + (size_t)gm * XB_COLS + bc * BN + tx * TN;
#pragma unroll
            for (int j = 0; j < TN; j += 4)
                *(float4*)(dst + j) = make_float4(acc[i][j], acc[i][j + 1], acc[i][j + 2], acc[i][j + 3]);
        }
    }
}

// ---------------- s[n,r] = sum_b coef[r,b] * (att . xb[n,b,:]) ----------------
__global__ __launch_bounds__(256) void k_s(const float* __restrict__ att,
                                           const float* __restrict__ coef) {
    int node = (blockIdx.x * blockDim.x + threadIdx.x) >> 5;
    int lane = threadIdx.x & 31;
    if (node >= N_NODES) return;
    const float* row = g_xb + (size_t)node * XB_COLS;
    float a0 = att[lane], a1 = att[lane + 32], a2 = att[lane + 64], a3 = att[lane + 96];
    float t[NB];
#pragma unroll
    for (int b = 0; b < NB; b++) {
        const float* p = row + b * D;
        float v = a0 * p[lane] + a1 * p[lane + 32] + a2 * p[lane + 64] + a3 * p[lane + 96];
#pragma unroll
        for (int off = 16; off; off >>= 1) v += __shfl_xor_sync(0xffffffffu, v, off);
        t[b] = v;
    }
    float sv = 0.f;
#pragma unroll
    for (int b = 0; b < NB; b++) sv += coef[lane * NB + b] * t[b];
    g_s[(size_t)node * R + lane] = sv;
}

// ---------------- edge pass 1: ex = exp(leaky(s_src+s_dst)); denom[dst] += ex ----------------
__global__ __launch_bounds__(256) void k_edge1(const int* __restrict__ src,
                                               const int* __restrict__ dst,
                                               const int* __restrict__ rel) {
    int e = blockIdx.x * blockDim.x + threadIdx.x;
    if (e >= N_EDGES) return;
    int sN = src[e], dN = dst[e], rr = rel[e];
    float sc = g_s[(size_t)sN * R + rr] + g_s[(size_t)dN * R + rr];
    sc = (sc >= 0.f) ? sc : 0.01f * sc;
    float ez = expf(sc);
    g_ex[e] = ez;
    atomicAdd(&g_denom[dN], ez);
}

// ---------------- edge pass 2: accum[dst] += (ex/denom[dst]) * src_r ----------------
// warp per edge; src_r computed on the fly: sum_b coef[rel,b] * xb[src,b,:]
__global__ __launch_bounds__(256) void k_edge2(const int* __restrict__ src,
                                               const int* __restrict__ dst,
                                               const int* __restrict__ rel,
                                               const float* __restrict__ coef) {
    int e = (blockIdx.x * blockDim.x + threadIdx.x) >> 5;
    int lane = threadIdx.x & 31;
    if (e >= N_EDGES) return;
    int sN = src[e], dN = dst[e], rr = rel[e];
    float w = g_ex[e] / g_denom[dN];
    float c[NB];
#pragma unroll
    for (int b = 0; b < NB; b++) c[b] = coef[rr * NB + b];
    const float4* xp = (const float4*)(g_xb + (size_t)sN * XB_COLS);
    float4 acc = make_float4(0.f, 0.f, 0.f, 0.f);
#pragma unroll
    for (int b = 0; b < NB; b++) {
        float4 v = xp[b * 32 + lane];
        acc.x += c[b] * v.x;
        acc.y += c[b] * v.y;
        acc.z += c[b] * v.z;
        acc.w += c[b] * v.w;
    }
    acc.x *= w; acc.y *= w; acc.z *= w; acc.w *= w;
    atomicAdd((float4*)(g_accum + (size_t)dN * D + lane * 4), acc);
}

// ---------------- ft = accum*norm + bias + loop; column stats partials ----------------
__global__ __launch_bounds__(128) void k_ft(const float* __restrict__ norm,
                                            const float* __restrict__ bias) {
    int o = threadIdx.x;  // column
    float b = bias[o];
    float lsum = 0.f, lsq = 0.f;
    for (int n = blockIdx.x; n < N_NODES; n += gridDim.x) {
        float v = g_accum[(size_t)n * D + o] * norm[n] + b + g_xb[(size_t)n * XB_COLS + 8 * D + o];
        g_ft[(size_t)n * D + o] = v;
        lsum += v;
        lsq += v * v;
    }
    atomicAdd(&g_colsum[o], lsum);
    atomicAdd(&g_colsumsq[o], lsq);
}

// ---------------- BN finalize: scale/shift ----------------
__global__ void k_bn(const float* __restrict__ gamma, const float* __restrict__ beta) {
    int o = threadIdx.x;
    float mu = g_colsum[o] / (float)N_NODES;
    float var = g_colsumsq[o] / (float)N_NODES - mu * mu;
    float inv = rsqrtf(var + 1e-5f);
    float sc = gamma[o] * inv;
    g_scale[o] = sc;
    g_shift[o] = beta[o] - mu * sc;
}

// ---------------- output: relu(ft*scale + shift) ----------------
__global__ __launch_bounds__(256) void k_out(float* __restrict__ out) {
    int i = blockIdx.x * blockDim.x + threadIdx.x;
    int total = N_NODES * D / 4;
    if (i >= total) return;
    float4 v = ((const float4*)g_ft)[i];
    int o = (i * 4) & (D - 1);
    float4 r;
    r.x = fmaxf(0.f, v.x * g_scale[o + 0] + g_shift[o + 0]);
    r.y = fmaxf(0.f, v.y * g_scale[o + 1] + g_shift[o + 1]);
    r.z = fmaxf(0.f, v.z * g_scale[o + 2] + g_shift[o + 2]);
    r.w = fmaxf(0.f, v.w * g_scale[o + 3] + g_shift[o + 3]);
    ((float4*)out)[i] = r;
}

extern "C" void kernel_launch(void* const* d_in, const int* in_sizes, int n_in,
                              void* d_out, int out_size) {
    const float* x       = (const float*)d_in[0];
    const float* norm    = (const float*)d_in[1];
    const int*   esrc    = (const int*)d_in[2];
    const int*   edst    = (const int*)d_in[3];
    const int*   erel    = (const int*)d_in[4];
    // d_in[5] = w_loop, d_in[6] = w_bases
    const float* w_loop  = (const float*)d_in[5];
    const float* w_bases = (const float*)d_in[6];
    const float* coef    = (const float*)d_in[7];
    const float* att     = (const float*)d_in[8];
    const float* bias    = (const float*)d_in[9];
    const float* gamma   = (const float*)d_in[10];
    const float* beta    = (const float*)d_in[11];
    float* out = (float*)d_out;

    k_zero<<<2048, 256>>>();

    dim3 gg(9, (N_NODES + BM - 1) / BM);
    k_gemm<<<gg, 256>>>(x, w_bases, w_loop);

    k_s<<<(N_NODES * 32 + 255) / 256, 256>>>(att, coef);

    k_edge1<<<(N_EDGES + 255) / 256, 256>>>(esrc, edst, erel);

    k_edge2<<<(N_EDGES * 32 + 255) / 256, 256>>>(esrc, edst, erel, coef);

    k_ft<<<512, 128>>>(norm, bias);

    k_bn<<<1, 128>>>(gamma, beta);

    k_out<<<(N_NODES * D / 4 + 255) / 256, 256>>>(out);
}

// round 3
// speedup vs baseline: 1.2412x; 1.2412x over previous
#include <cuda_runtime.h>
#include <cuda_bf16.h>
#include <cstdint>
#include <math.h>

#define N_NODES 40000
#define N_EDGES 640000
#define D 128
#define R 32
#define NB 8
#define XB_COLS 1152   // 9*128: 8 bases + loop

// ---- scratch (static device globals; no runtime allocation) ----
__device__ float g_xb[(size_t)N_NODES * XB_COLS];   // 184 MB
__device__ float g_s[(size_t)N_NODES * R];          // 5.1 MB
__device__ float g_attdot[(size_t)N_NODES * NB];    // 1.28 MB
__device__ float g_ex[N_EDGES];
__device__ float g_denom[N_NODES];
__device__ float g_accum[(size_t)N_NODES * D];      // 20.5 MB
__device__ float g_ft[(size_t)N_NODES * D];         // 20.5 MB
__device__ float g_colsum[D];
__device__ float g_colsumsq[D];
__device__ float g_scale[D];
__device__ float g_shift[D];
__device__ __nv_bfloat16 g_xhi[(size_t)N_NODES * D];
__device__ __nv_bfloat16 g_xlo[(size_t)N_NODES * D];
__device__ __nv_bfloat16 g_wthi[9 * D * D];         // [b][n][k]  (W^T, k contiguous)
__device__ __nv_bfloat16 g_wtlo[9 * D * D];

// ================= conversion kernels =================
__global__ void k_convx(const float* __restrict__ x) {
    int i = blockIdx.x * blockDim.x + threadIdx.x;
    if (i >= N_NODES * D) return;
    float v = x[i];
    __nv_bfloat16 h = __float2bfloat16(v);
    g_xhi[i] = h;
    g_xlo[i] = __float2bfloat16(v - __bfloat162float(h));
}

__global__ void k_convw(const float* __restrict__ w_bases, const float* __restrict__ w_loop) {
    int i = blockIdx.x * blockDim.x + threadIdx.x;
    if (i >= 9 * D * D) return;
    int b = i >> 14;
    int rem = i & 16383;
    int n = rem >> 7;
    int k = rem & 127;
    float v = (b < 8) ? w_bases[(b << 14) + k * D + n] : w_loop[k * D + n];
    __nv_bfloat16 h = __float2bfloat16(v);
    g_wthi[i] = h;
    g_wtlo[i] = __float2bfloat16(v - __bfloat162float(h));
}

// ================= mma.sync bf16 GEMM: xb = x @ [Wb | Wloop] =================
// Grid: (313 m-tiles, 9 bases). CTA = 256 thr = 8 warps (4 m x 2 n).
// Per CTA output: 128x128 fp32. K=128, 3 hi/lo passes (hh, hl, lh).
// SMEM tiles padded to 40 bf16/row (80B) -> conflict-free ldmatrix.

#define PAD 40

__global__ __launch_bounds__(256, 2) void k_gemm_mma(const float* __restrict__ att) {
    __shared__ __align__(16) __nv_bfloat16 As[128 * PAD];
    __shared__ __align__(16) __nv_bfloat16 Bs[128 * PAD];
    __shared__ float atts[128];

    const int tid = threadIdx.x;
    const int lane = tid & 31;
    const int wid = tid >> 5;
    const int wm = wid & 3;       // 0..3 : 32-row strip
    const int wn = wid >> 2;      // 0..1 : 64-col strip
    const int m0 = blockIdx.x * 128;
    const int b = blockIdx.y;

    if (tid < 128) atts[tid] = att[tid];

    float acc[2][8][4];
#pragma unroll
    for (int mf = 0; mf < 2; mf++)
#pragma unroll
        for (int nf = 0; nf < 8; nf++)
#pragma unroll
            for (int r = 0; r < 4; r++) acc[mf][nf][r] = 0.f;

    // ldmatrix lane->address components
    const int a_row = wm * 32 + (lane & 15);
    const int a_cb = (lane >> 4) << 3;          // 0 or 8 (k offset)
    const int b_row = wn * 64 + (lane & 7) + ((lane >> 4) << 3);
    const int b_cb = (lane & 8);                // 0 or 8 (k offset)

    for (int p = 0; p < 3; p++) {
        const __nv_bfloat16* Ag = (p == 2) ? g_xlo : g_xhi;
        const __nv_bfloat16* Bg = ((p == 1) ? g_wtlo : g_wthi) + b * (D * D);
#pragma unroll 1
        for (int kc = 0; kc < 4; kc++) {
            const int k0 = kc * 32;
            __syncthreads();
#pragma unroll
            for (int l = 0; l < 2; l++) {
                int i = l * 256 + tid;          // 0..511
                int row = i >> 2;               // 0..127
                int c8 = (i & 3) * 8;           // 0,8,16,24
                int g = m0 + row;
                uint4 v = make_uint4(0, 0, 0, 0);
                if (g < N_NODES) v = *(const uint4*)(Ag + (size_t)g * D + k0 + c8);
                *(uint4*)(As + row * PAD + c8) = v;
                *(uint4*)(Bs + row * PAD + c8) = *(const uint4*)(Bg + row * D + k0 + c8);
            }
            __syncthreads();
#pragma unroll
            for (int ks = 0; ks < 2; ks++) {
                const int kk = ks * 16;
                uint32_t a[2][4];
#pragma unroll
                for (int mf = 0; mf < 2; mf++) {
                    uint32_t addr = (uint32_t)__cvta_generic_to_shared(
                        As + (a_row + mf * 16) * PAD + kk + a_cb);
                    asm volatile("ldmatrix.sync.aligned.m8n8.x4.shared.b16 {%0,%1,%2,%3}, [%4];"
                        : "=r"(a[mf][0]), "=r"(a[mf][1]), "=r"(a[mf][2]), "=r"(a[mf][3])
                        : "r"(addr));
                }
                uint32_t bf[8][2];
#pragma unroll
                for (int nf2 = 0; nf2 < 4; nf2++) {
                    uint32_t addr = (uint32_t)__cvta_generic_to_shared(
                        Bs + (b_row + nf2 * 16) * PAD + kk + b_cb);
                    asm volatile("ldmatrix.sync.aligned.m8n8.x4.shared.b16 {%0,%1,%2,%3}, [%4];"
                        : "=r"(bf[nf2 * 2][0]), "=r"(bf[nf2 * 2][1]),
                          "=r"(bf[nf2 * 2 + 1][0]), "=r"(bf[nf2 * 2 + 1][1])
                        : "r"(addr));
                }
#pragma unroll
                for (int mf = 0; mf < 2; mf++)
#pragma unroll
                    for (int nf = 0; nf < 8; nf++)
                        asm volatile(
                            "mma.sync.aligned.m16n8k16.row.col.f32.bf16.bf16.f32 "
                            "{%0,%1,%2,%3}, {%4,%5,%6,%7}, {%8,%9}, {%0,%1,%2,%3};"
                            : "+f"(acc[mf][nf][0]), "+f"(acc[mf][nf][1]),
                              "+f"(acc[mf][nf][2]), "+f"(acc[mf][nf][3])
                            : "r"(a[mf][0]), "r"(a[mf][1]), "r"(a[mf][2]), "r"(a[mf][3]),
                              "r"(bf[nf][0]), "r"(bf[nf][1]));
            }
        }
    }

    // ---- epilogue: store xb + fused attention dot ----
#pragma unroll
    for (int mf = 0; mf < 2; mf++) {
        int r1 = m0 + wm * 32 + mf * 16 + (lane >> 2);
        int r2 = r1 + 8;
#pragma unroll
        for (int nf = 0; nf < 8; nf++) {
            int col = wn * 64 + nf * 8 + (lane & 3) * 2;
            if (r1 < N_NODES)
                *(float2*)(g_xb + (size_t)r1 * XB_COLS + b * 128 + col) =
                    make_float2(acc[mf][nf][0], acc[mf][nf][1]);
            if (r2 < N_NODES)
                *(float2*)(g_xb + (size_t)r2 * XB_COLS + b * 128 + col) =
                    make_float2(acc[mf][nf][2], acc[mf][nf][3]);
        }
    }
    if (b < 8) {
        float ad[4] = {0.f, 0.f, 0.f, 0.f};
#pragma unroll
        for (int mf = 0; mf < 2; mf++)
#pragma unroll
            for (int nf = 0; nf < 8; nf++) {
                int col = wn * 64 + nf * 8 + (lane & 3) * 2;
                float a0 = atts[col], a1 = atts[col + 1];
                ad[mf * 2 + 0] = fmaf(a0, acc[mf][nf][0], fmaf(a1, acc[mf][nf][1], ad[mf * 2 + 0]));
                ad[mf * 2 + 1] = fmaf(a0, acc[mf][nf][2], fmaf(a1, acc[mf][nf][3], ad[mf * 2 + 1]));
            }
#pragma unroll
        for (int off = 1; off <= 2; off <<= 1)
#pragma unroll
            for (int j = 0; j < 4; j++) ad[j] += __shfl_xor_sync(0xffffffffu, ad[j], off);
        if ((lane & 3) == 0) {
            int rbase = m0 + wm * 32 + (lane >> 2);
#pragma unroll
            for (int mf = 0; mf < 2; mf++) {
                int g1 = rbase + mf * 16;
                if (g1 < N_NODES) atomicAdd(&g_attdot[(size_t)g1 * NB + b], ad[mf * 2 + 0]);
                if (g1 + 8 < N_NODES) atomicAdd(&g_attdot[(size_t)(g1 + 8) * NB + b], ad[mf * 2 + 1]);
            }
        }
    }
}

// ---------------- zero init (graph-replay safe) ----------------
__global__ void k_zero() {
    int idx = blockIdx.x * blockDim.x + threadIdx.x;
    int stride = gridDim.x * blockDim.x;
    for (int j = idx; j < N_NODES * D; j += stride) g_accum[j] = 0.f;
    for (int j = idx; j < N_NODES * NB; j += stride) g_attdot[j] = 0.f;
    for (int j = idx; j < N_NODES; j += stride) g_denom[j] = 0.f;
    if (idx < D) { g_colsum[idx] = 0.f; g_colsumsq[idx] = 0.f; }
}

// ---------------- s[n,r] = sum_b coef[r,b] * attdot[n,b] ----------------
__global__ __launch_bounds__(256) void k_s2(const float* __restrict__ coef) {
    int t = blockIdx.x * blockDim.x + threadIdx.x;
    int node = t >> 5;
    int r = t & 31;
    if (node >= N_NODES) return;
    const float* ad = g_attdot + (size_t)node * NB;
    float s = 0.f;
#pragma unroll
    for (int b = 0; b < NB; b++) s = fmaf(coef[r * NB + b], ad[b], s);
    g_s[(size_t)node * R + r] = s;
}

// ---------------- edge pass 1 ----------------
__global__ __launch_bounds__(256) void k_edge1(const int* __restrict__ src,
                                               const int* __restrict__ dst,
                                               const int* __restrict__ rel) {
    int e = blockIdx.x * blockDim.x + threadIdx.x;
    if (e >= N_EDGES) return;
    int sN = src[e], dN = dst[e], rr = rel[e];
    float sc = g_s[(size_t)sN * R + rr] + g_s[(size_t)dN * R + rr];
    sc = (sc >= 0.f) ? sc : 0.01f * sc;
    float ez = expf(sc);
    g_ex[e] = ez;
    atomicAdd(&g_denom[dN], ez);
}

// ---------------- edge pass 2 ----------------
__global__ __launch_bounds__(256) void k_edge2(const int* __restrict__ src,
                                               const int* __restrict__ dst,
                                               const int* __restrict__ rel,
                                               const float* __restrict__ coef) {
    int e = (blockIdx.x * blockDim.x + threadIdx.x) >> 5;
    int lane = threadIdx.x & 31;
    if (e >= N_EDGES) return;
    int sN = src[e], dN = dst[e], rr = rel[e];
    float w = g_ex[e] / g_denom[dN];
    float c[NB];
#pragma unroll
    for (int b = 0; b < NB; b++) c[b] = coef[rr * NB + b];
    const float4* xp = (const float4*)(g_xb + (size_t)sN * XB_COLS);
    float4 acc = make_float4(0.f, 0.f, 0.f, 0.f);
#pragma unroll
    for (int b = 0; b < NB; b++) {
        float4 v = xp[b * 32 + lane];
        acc.x += c[b] * v.x;
        acc.y += c[b] * v.y;
        acc.z += c[b] * v.z;
        acc.w += c[b] * v.w;
    }
    acc.x *= w; acc.y *= w; acc.z *= w; acc.w *= w;
    atomicAdd((float4*)(g_accum + (size_t)dN * D + lane * 4), acc);
}

// ---------------- ft + column stats ----------------
__global__ __launch_bounds__(128) void k_ft(const float* __restrict__ norm,
                                            const float* __restrict__ bias) {
    int o = threadIdx.x;
    float b = bias[o];
    float lsum = 0.f, lsq = 0.f;
    for (int n = blockIdx.x; n < N_NODES; n += gridDim.x) {
        float v = g_accum[(size_t)n * D + o] * norm[n] + b + g_xb[(size_t)n * XB_COLS + 8 * D + o];
        g_ft[(size_t)n * D + o] = v;
        lsum += v;
        lsq += v * v;
    }
    atomicAdd(&g_colsum[o], lsum);
    atomicAdd(&g_colsumsq[o], lsq);
}

// ---------------- BN finalize ----------------
__global__ void k_bn(const float* __restrict__ gamma, const float* __restrict__ beta) {
    int o = threadIdx.x;
    float mu = g_colsum[o] / (float)N_NODES;
    float var = g_colsumsq[o] / (float)N_NODES - mu * mu;
    float inv = rsqrtf(var + 1e-5f);
    float sc = gamma[o] * inv;
    g_scale[o] = sc;
    g_shift[o] = beta[o] - mu * sc;
}

// ---------------- output ----------------
__global__ __launch_bounds__(256) void k_out(float* __restrict__ out) {
    int i = blockIdx.x * blockDim.x + threadIdx.x;
    int total = N_NODES * D / 4;
    if (i >= total) return;
    float4 v = ((const float4*)g_ft)[i];
    int o = (i * 4) & (D - 1);
    float4 r;
    r.x = fmaxf(0.f, v.x * g_scale[o + 0] + g_shift[o + 0]);
    r.y = fmaxf(0.f, v.y * g_scale[o + 1] + g_shift[o + 1]);
    r.z = fmaxf(0.f, v.z * g_scale[o + 2] + g_shift[o + 2]);
    r.w = fmaxf(0.f, v.w * g_scale[o + 3] + g_shift[o + 3]);
    ((float4*)out)[i] = r;
}

extern "C" void kernel_launch(void* const* d_in, const int* in_sizes, int n_in,
                              void* d_out, int out_size) {
    const float* x       = (const float*)d_in[0];
    const float* norm    = (const float*)d_in[1];
    const int*   esrc    = (const int*)d_in[2];
    const int*   edst    = (const int*)d_in[3];
    const int*   erel    = (const int*)d_in[4];
    const float* w_loop  = (const float*)d_in[5];
    const float* w_bases = (const float*)d_in[6];
    const float* coef    = (const float*)d_in[7];
    const float* att     = (const float*)d_in[8];
    const float* bias    = (const float*)d_in[9];
    const float* gamma   = (const float*)d_in[10];
    const float* beta    = (const float*)d_in[11];
    float* out = (float*)d_out;

    k_zero<<<2048, 256>>>();
    k_convx<<<(N_NODES * D + 255) / 256, 256>>>(x);
    k_convw<<<(9 * D * D + 255) / 256, 256>>>(w_bases, w_loop);

    dim3 gg((N_NODES + 127) / 128, 9);
    k_gemm_mma<<<gg, 256>>>(att);

    k_s2<<<(N_NODES * 32 + 255) / 256, 256>>>(coef);
    k_edge1<<<(N_EDGES + 255) / 256, 256>>>(esrc, edst, erel);
    k_edge2<<<(N_EDGES * 32 + 255) / 256, 256>>>(esrc, edst, erel, coef);
    k_ft<<<512, 128>>>(norm, bias);
    k_bn<<<1, 128>>>(gamma, beta);
    k_out<<<(N_NODES * D / 4 + 255) / 256, 256>>>(out);
}

// round 4
// speedup vs baseline: 1.7580x; 1.4163x over previous
#include <cuda_runtime.h>
#include <cuda_bf16.h>
#include <cuda_fp16.h>
#include <cstdint>
#include <math.h>

#define N_NODES 40000
#define N_EDGES 640000
#define D 128
#define R 32
#define NB 8

// ---- scratch (static device globals; no runtime allocation) ----
__device__ __half g_xbh[(size_t)N_NODES * NB * D];  // 82 MB: bases 0-7, fp16
__device__ float g_xloop[(size_t)N_NODES * D];      // 20.5 MB: loop block fp32
__device__ float g_s[(size_t)N_NODES * R];          // 5.1 MB
__device__ float g_attdot[(size_t)N_NODES * NB];    // 1.28 MB
__device__ float g_ex[N_EDGES];
__device__ float g_denom[N_NODES];
__device__ float g_accum[(size_t)N_NODES * D];      // 20.5 MB
__device__ float g_ft[(size_t)N_NODES * D];         // 20.5 MB
__device__ float g_colsum[D];
__device__ float g_colsumsq[D];
__device__ float g_scale[D];
__device__ float g_shift[D];
__device__ __nv_bfloat16 g_xhi[(size_t)N_NODES * D];
__device__ __nv_bfloat16 g_xlo[(size_t)N_NODES * D];
__device__ __nv_bfloat16 g_wthi[9 * D * D];         // [b][n][k]  (W^T, k contiguous)
__device__ __nv_bfloat16 g_wtlo[9 * D * D];

// ================= conversion kernels =================
__global__ void k_convx(const float* __restrict__ x) {
    int i = blockIdx.x * blockDim.x + threadIdx.x;
    if (i >= N_NODES * D) return;
    float v = x[i];
    __nv_bfloat16 h = __float2bfloat16(v);
    g_xhi[i] = h;
    g_xlo[i] = __float2bfloat16(v - __bfloat162float(h));
}

__global__ void k_convw(const float* __restrict__ w_bases, const float* __restrict__ w_loop) {
    int i = blockIdx.x * blockDim.x + threadIdx.x;
    if (i >= 9 * D * D) return;
    int b = i >> 14;
    int rem = i & 16383;
    int n = rem >> 7;
    int k = rem & 127;
    float v = (b < 8) ? w_bases[(b << 14) + k * D + n] : w_loop[k * D + n];
    __nv_bfloat16 h = __float2bfloat16(v);
    g_wthi[i] = h;
    g_wtlo[i] = __float2bfloat16(v - __bfloat162float(h));
}

// ================= mma.sync bf16 GEMM (single pass, hi/lo resident) =================
// Grid: (313 m-tiles, 9 bases). CTA = 256 thr = 8 warps (4 m x 2 n).
// Per k-chunk: load Ahi/Alo/Bhi/Blo tiles once; 3 MMA groups: hh, hl, lh.

#define PAD 40

__global__ __launch_bounds__(256, 2) void k_gemm_mma(const float* __restrict__ att) {
    __shared__ __align__(16) __nv_bfloat16 Ah[128 * PAD];
    __shared__ __align__(16) __nv_bfloat16 Al[128 * PAD];
    __shared__ __align__(16) __nv_bfloat16 Bh[128 * PAD];
    __shared__ __align__(16) __nv_bfloat16 Bl[128 * PAD];
    __shared__ float atts[128];

    const int tid = threadIdx.x;
    const int lane = tid & 31;
    const int wid = tid >> 5;
    const int wm = wid & 3;       // 0..3 : 32-row strip
    const int wn = wid >> 2;      // 0..1 : 64-col strip
    const int m0 = blockIdx.x * 128;
    const int b = blockIdx.y;

    if (tid < 128) atts[tid] = att[tid];

    float acc[2][8][4];
#pragma unroll
    for (int mf = 0; mf < 2; mf++)
#pragma unroll
        for (int nf = 0; nf < 8; nf++)
#pragma unroll
            for (int r = 0; r < 4; r++) acc[mf][nf][r] = 0.f;

    const int a_row = wm * 32 + (lane & 15);
    const int a_cb = (lane >> 4) << 3;
    const int b_row = wn * 64 + (lane & 7) + ((lane >> 4) << 3);
    const int b_cb = (lane & 8);

    const __nv_bfloat16* Bgh = g_wthi + b * (D * D);
    const __nv_bfloat16* Bgl = g_wtlo + b * (D * D);

#pragma unroll 1
    for (int kc = 0; kc < 4; kc++) {
        const int k0 = kc * 32;
        __syncthreads();
        // fill 4 tiles: 2048 uint4 slots, 8 per thread
#pragma unroll
        for (int l = 0; l < 2; l++) {
            int i = l * 256 + tid;          // 0..511 per tile
            int row = i >> 2;
            int c8 = (i & 3) * 8;
            int g = m0 + row;
            uint4 vh = make_uint4(0, 0, 0, 0), vl = make_uint4(0, 0, 0, 0);
            if (g < N_NODES) {
                vh = *(const uint4*)(g_xhi + (size_t)g * D + k0 + c8);
                vl = *(const uint4*)(g_xlo + (size_t)g * D + k0 + c8);
            }
            *(uint4*)(Ah + row * PAD + c8) = vh;
            *(uint4*)(Al + row * PAD + c8) = vl;
            *(uint4*)(Bh + row * PAD + c8) = *(const uint4*)(Bgh + row * D + k0 + c8);
            *(uint4*)(Bl + row * PAD + c8) = *(const uint4*)(Bgl + row * D + k0 + c8);
        }
        __syncthreads();
#pragma unroll
        for (int ks = 0; ks < 2; ks++) {
            const int kk = ks * 16;
            uint32_t ah[2][4], al[2][4];
#pragma unroll
            for (int mf = 0; mf < 2; mf++) {
                uint32_t addr = (uint32_t)__cvta_generic_to_shared(
                    Ah + (a_row + mf * 16) * PAD + kk + a_cb);
                asm volatile("ldmatrix.sync.aligned.m8n8.x4.shared.b16 {%0,%1,%2,%3}, [%4];"
                    : "=r"(ah[mf][0]), "=r"(ah[mf][1]), "=r"(ah[mf][2]), "=r"(ah[mf][3])
                    : "r"(addr));
                addr = (uint32_t)__cvta_generic_to_shared(
                    Al + (a_row + mf * 16) * PAD + kk + a_cb);
                asm volatile("ldmatrix.sync.aligned.m8n8.x4.shared.b16 {%0,%1,%2,%3}, [%4];"
                    : "=r"(al[mf][0]), "=r"(al[mf][1]), "=r"(al[mf][2]), "=r"(al[mf][3])
                    : "r"(addr));
            }
            uint32_t bh[8][2], bl[8][2];
#pragma unroll
            for (int nf2 = 0; nf2 < 4; nf2++) {
                uint32_t addr = (uint32_t)__cvta_generic_to_shared(
                    Bh + (b_row + nf2 * 16) * PAD + kk + b_cb);
                asm volatile("ldmatrix.sync.aligned.m8n8.x4.shared.b16 {%0,%1,%2,%3}, [%4];"
                    : "=r"(bh[nf2 * 2][0]), "=r"(bh[nf2 * 2][1]),
                      "=r"(bh[nf2 * 2 + 1][0]), "=r"(bh[nf2 * 2 + 1][1])
                    : "r"(addr));
                addr = (uint32_t)__cvta_generic_to_shared(
                    Bl + (b_row + nf2 * 16) * PAD + kk + b_cb);
                asm volatile("ldmatrix.sync.aligned.m8n8.x4.shared.b16 {%0,%1,%2,%3}, [%4];"
                    : "=r"(bl[nf2 * 2][0]), "=r"(bl[nf2 * 2][1]),
                      "=r"(bl[nf2 * 2 + 1][0]), "=r"(bl[nf2 * 2 + 1][1])
                    : "r"(addr));
            }
#define MMA(ar, br) \
    asm volatile("mma.sync.aligned.m16n8k16.row.col.f32.bf16.bf16.f32 " \
        "{%0,%1,%2,%3}, {%4,%5,%6,%7}, {%8,%9}, {%0,%1,%2,%3};" \
        : "+f"(acc[mf][nf][0]), "+f"(acc[mf][nf][1]), \
          "+f"(acc[mf][nf][2]), "+f"(acc[mf][nf][3]) \
        : "r"((ar)[0]), "r"((ar)[1]), "r"((ar)[2]), "r"((ar)[3]), \
          "r"((br)[0]), "r"((br)[1]))
#pragma unroll
            for (int mf = 0; mf < 2; mf++)
#pragma unroll
                for (int nf = 0; nf < 8; nf++) {
                    MMA(ah[mf], bh[nf]);
                    MMA(ah[mf], bl[nf]);
                    MMA(al[mf], bh[nf]);
                }
#undef MMA
        }
    }

    // ---- epilogue ----
    if (b < 8) {
        // fp16 store for edge-gather path
#pragma unroll
        for (int mf = 0; mf < 2; mf++) {
            int r1 = m0 + wm * 32 + mf * 16 + (lane >> 2);
            int r2 = r1 + 8;
#pragma unroll
            for (int nf = 0; nf < 8; nf++) {
                int col = wn * 64 + nf * 8 + (lane & 3) * 2;
                if (r1 < N_NODES)
                    *(__half2*)(g_xbh + (size_t)r1 * (NB * D) + b * D + col) =
                        __floats2half2_rn(acc[mf][nf][0], acc[mf][nf][1]);
                if (r2 < N_NODES)
                    *(__half2*)(g_xbh + (size_t)r2 * (NB * D) + b * D + col) =
                        __floats2half2_rn(acc[mf][nf][2], acc[mf][nf][3]);
            }
        }
        // fused attention dot (fp32 accumulators)
        float ad[4] = {0.f, 0.f, 0.f, 0.f};
#pragma unroll
        for (int mf = 0; mf < 2; mf++)
#pragma unroll
            for (int nf = 0; nf < 8; nf++) {
                int col = wn * 64 + nf * 8 + (lane & 3) * 2;
                float a0 = atts[col], a1 = atts[col + 1];
                ad[mf * 2 + 0] = fmaf(a0, acc[mf][nf][0], fmaf(a1, acc[mf][nf][1], ad[mf * 2 + 0]));
                ad[mf * 2 + 1] = fmaf(a0, acc[mf][nf][2], fmaf(a1, acc[mf][nf][3], ad[mf * 2 + 1]));
            }
#pragma unroll
        for (int off = 1; off <= 2; off <<= 1)
#pragma unroll
            for (int j = 0; j < 4; j++) ad[j] += __shfl_xor_sync(0xffffffffu, ad[j], off);
        if ((lane & 3) == 0) {
            int rbase = m0 + wm * 32 + (lane >> 2);
#pragma unroll
            for (int mf = 0; mf < 2; mf++) {
                int g1 = rbase + mf * 16;
                if (g1 < N_NODES) atomicAdd(&g_attdot[(size_t)g1 * NB + b], ad[mf * 2 + 0]);
                if (g1 + 8 < N_NODES) atomicAdd(&g_attdot[(size_t)(g1 + 8) * NB + b], ad[mf * 2 + 1]);
            }
        }
    } else {
        // loop block: fp32
#pragma unroll
        for (int mf = 0; mf < 2; mf++) {
            int r1 = m0 + wm * 32 + mf * 16 + (lane >> 2);
            int r2 = r1 + 8;
#pragma unroll
            for (int nf = 0; nf < 8; nf++) {
                int col = wn * 64 + nf * 8 + (lane & 3) * 2;
                if (r1 < N_NODES)
                    *(float2*)(g_xloop + (size_t)r1 * D + col) =
                        make_float2(acc[mf][nf][0], acc[mf][nf][1]);
                if (r2 < N_NODES)
                    *(float2*)(g_xloop + (size_t)r2 * D + col) =
                        make_float2(acc[mf][nf][2], acc[mf][nf][3]);
            }
        }
    }
}

// ---------------- zero init (graph-replay safe) ----------------
__global__ void k_zero() {
    int idx = blockIdx.x * blockDim.x + threadIdx.x;
    int stride = gridDim.x * blockDim.x;
    for (int j = idx; j < N_NODES * D; j += stride) g_accum[j] = 0.f;
    for (int j = idx; j < N_NODES * NB; j += stride) g_attdot[j] = 0.f;
    for (int j = idx; j < N_NODES; j += stride) g_denom[j] = 0.f;
    if (idx < D) { g_colsum[idx] = 0.f; g_colsumsq[idx] = 0.f; }
}

// ---------------- s[n,r] = sum_b coef[r,b] * attdot[n,b] ----------------
__global__ __launch_bounds__(256) void k_s2(const float* __restrict__ coef) {
    int t = blockIdx.x * blockDim.x + threadIdx.x;
    int node = t >> 5;
    int r = t & 31;
    if (node >= N_NODES) return;
    const float* ad = g_attdot + (size_t)node * NB;
    float s = 0.f;
#pragma unroll
    for (int b = 0; b < NB; b++) s = fmaf(coef[r * NB + b], ad[b], s);
    g_s[(size_t)node * R + r] = s;
}

// ---------------- edge pass 1 ----------------
__global__ __launch_bounds__(256) void k_edge1(const int* __restrict__ src,
                                               const int* __restrict__ dst,
                                               const int* __restrict__ rel) {
    int e = blockIdx.x * blockDim.x + threadIdx.x;
    if (e >= N_EDGES) return;
    int sN = src[e], dN = dst[e], rr = rel[e];
    float sc = g_s[(size_t)sN * R + rr] + g_s[(size_t)dN * R + rr];
    sc = (sc >= 0.f) ? sc : 0.01f * sc;
    float ez = expf(sc);
    g_ex[e] = ez;
    atomicAdd(&g_denom[dN], ez);
}

// ---------------- edge pass 2: fp16 gather (L2-resident) ----------------
__global__ __launch_bounds__(256) void k_edge2(const int* __restrict__ src,
                                               const int* __restrict__ dst,
                                               const int* __restrict__ rel,
                                               const float* __restrict__ coef) {
    int e = (blockIdx.x * blockDim.x + threadIdx.x) >> 5;
    int lane = threadIdx.x & 31;
    if (e >= N_EDGES) return;
    int sN = src[e], dN = dst[e], rr = rel[e];
    float w = g_ex[e] / g_denom[dN];
    float c[NB];
#pragma unroll
    for (int b = 0; b < NB; b++) c[b] = coef[rr * NB + b];
    const uint2* xp = (const uint2*)(g_xbh + (size_t)sN * (NB * D)) + lane;  // 4 halfs/lane/base
    float4 acc = make_float4(0.f, 0.f, 0.f, 0.f);
#pragma unroll
    for (int b = 0; b < NB; b++) {
        uint2 u = xp[b * 32];
        float2 f0 = __half22float2(*(const __half2*)&u.x);
        float2 f1 = __half22float2(*(const __half2*)&u.y);
        acc.x = fmaf(c[b], f0.x, acc.x);
        acc.y = fmaf(c[b], f0.y, acc.y);
        acc.z = fmaf(c[b], f1.x, acc.z);
        acc.w = fmaf(c[b], f1.y, acc.w);
    }
    acc.x *= w; acc.y *= w; acc.z *= w; acc.w *= w;
    atomicAdd((float4*)(g_accum + (size_t)dN * D + lane * 4), acc);
}

// ---------------- ft + column stats ----------------
__global__ __launch_bounds__(128) void k_ft(const float* __restrict__ norm,
                                            const float* __restrict__ bias) {
    int o = threadIdx.x;
    float b = bias[o];
    float lsum = 0.f, lsq = 0.f;
    for (int n = blockIdx.x; n < N_NODES; n += gridDim.x) {
        float v = g_accum[(size_t)n * D + o] * norm[n] + b + g_xloop[(size_t)n * D + o];
        g_ft[(size_t)n * D + o] = v;
        lsum += v;
        lsq += v * v;
    }
    atomicAdd(&g_colsum[o], lsum);
    atomicAdd(&g_colsumsq[o], lsq);
}

// ---------------- BN finalize ----------------
__global__ void k_bn(const float* __restrict__ gamma, const float* __restrict__ beta) {
    int o = threadIdx.x;
    float mu = g_colsum[o] / (float)N_NODES;
    float var = g_colsumsq[o] / (float)N_NODES - mu * mu;
    float inv = rsqrtf(var + 1e-5f);
    float sc = gamma[o] * inv;
    g_scale[o] = sc;
    g_shift[o] = beta[o] - mu * sc;
}

// ---------------- output ----------------
__global__ __launch_bounds__(256) void k_out(float* __restrict__ out) {
    int i = blockIdx.x * blockDim.x + threadIdx.x;
    int total = N_NODES * D / 4;
    if (i >= total) return;
    float4 v = ((const float4*)g_ft)[i];
    int o = (i * 4) & (D - 1);
    float4 r;
    r.x = fmaxf(0.f, v.x * g_scale[o + 0] + g_shift[o + 0]);
    r.y = fmaxf(0.f, v.y * g_scale[o + 1] + g_shift[o + 1]);
    r.z = fmaxf(0.f, v.z * g_scale[o + 2] + g_shift[o + 2]);
    r.w = fmaxf(0.f, v.w * g_scale[o + 3] + g_shift[o + 3]);
    ((float4*)out)[i] = r;
}

extern "C" void kernel_launch(void* const* d_in, const int* in_sizes, int n_in,
                              void* d_out, int out_size) {
    const float* x       = (const float*)d_in[0];
    const float* norm    = (const float*)d_in[1];
    const int*   esrc    = (const int*)d_in[2];
    const int*   edst    = (const int*)d_in[3];
    const int*   erel    = (const int*)d_in[4];
    const float* w_loop  = (const float*)d_in[5];
    const float* w_bases = (const float*)d_in[6];
    const float* coef    = (const float*)d_in[7];
    const float* att     = (const float*)d_in[8];
    const float* bias    = (const float*)d_in[9];
    const float* gamma   = (const float*)d_in[10];
    const float* beta    = (const float*)d_in[11];
    float* out = (float*)d_out;

    k_zero<<<2048, 256>>>();
    k_convx<<<(N_NODES * D + 255) / 256, 256>>>(x);
    k_convw<<<(9 * D * D + 255) / 256, 256>>>(w_bases, w_loop);

    dim3 gg((N_NODES + 127) / 128, 9);
    k_gemm_mma<<<gg, 256>>>(att);

    k_s2<<<(N_NODES * 32 + 255) / 256, 256>>>(coef);
    k_edge1<<<(N_EDGES + 255) / 256, 256>>>(esrc, edst, erel);
    k_edge2<<<(N_EDGES * 32 + 255) / 256, 256>>>(esrc, edst, erel, coef);
    k_ft<<<512, 128>>>(norm, bias);
    k_bn<<<1, 128>>>(gamma, beta);
    k_out<<<(N_NODES * D / 4 + 255) / 256, 256>>>(out);
}